// round 4
// baseline (speedup 1.0000x reference)
#include <cuda_runtime.h>
#include <math.h>

#define BB   32
#define NN   256
#define MM   64
#define FF   128
#define KK   64
#define RTOT (BB*NN)   // 8192

// -------- scratch (no allocations allowed) --------
__device__ float g_xa[RTOT*FF];
__device__ float g_v [RTOT*FF];
__device__ float g_t [RTOT*FF];

__device__ __forceinline__ float ssp(float x) {
    // softplus(x) - ln2, numerically stable (matches jax logaddexp(x,0) - ln2)
    float ax = fabsf(x);
    return fmaxf(x, 0.0f) + log1pf(__expf(-ax)) - 0.69314718055994530942f;
}

// -------- elementwise: xa = ssp(x) --------
__global__ void k_ssp(const float* __restrict__ x) {
    int i = blockIdx.x * blockDim.x + threadIdx.x;
    if (i < RTOT*FF) g_xa[i] = ssp(x[i]);
}

// -------- generic fused GEMM: out[r][c] = maybe_ssp( sum_k pre(in[r][k])*W[c][k] + b[c] ) (+ gate*res | res)
// 64 rows/CTA, 256 threads, 8x4 register tile, full K=128 staged in smem.
#define GRT 64
#define WLD 132   // W_s row stride (padded, 16B-aligned)
#define ALD 72    // A_s row stride (padded, 16B-aligned)

__global__ void __launch_bounds__(256) k_gemm(
    const float* __restrict__ in, const float* __restrict__ W,
    const float* __restrict__ b,  const float* __restrict__ res,
    const float* __restrict__ gate, float* __restrict__ out,
    int pre_act, int post_act)
{
    extern __shared__ float sm[];
    float* W_s = sm;               // [128][WLD]  W_s[k][c] = W[c][k]
    float* A_s = sm + FF*WLD;      // [128][ALD]  A_s[k][r]

    const int tid  = threadIdx.x;
    const int row0 = blockIdx.x * GRT;

    // load W transposed (coalesced global reads)
    for (int idx = tid; idx < FF*FF; idx += 256) {
        int c = idx >> 7, k = idx & 127;
        W_s[k*WLD + c] = W[idx];
    }
    // load A tile transposed with optional pre-activation
    for (int idx = tid; idx < GRT*FF; idx += 256) {
        int r = idx >> 7, k = idx & 127;
        float a = in[(size_t)row0*FF + idx];
        if (pre_act) a = ssp(a);
        A_s[k*ALD + r] = a;
    }
    __syncthreads();

    const int tx = tid & 31;   // col group: cols tx*4 .. tx*4+3
    const int ty = tid >> 5;   // row group: rows ty*8 .. ty*8+7

    float acc[8][4];
    #pragma unroll
    for (int i = 0; i < 8; i++)
        #pragma unroll
        for (int j = 0; j < 4; j++) acc[i][j] = 0.0f;

    const float* wp = W_s + tx*4;
    const float* ap = A_s + ty*8;

    #pragma unroll 4
    for (int k = 0; k < FF; k++) {
        float4 w4 = *(const float4*)(wp + k*WLD);
        float4 a0 = *(const float4*)(ap + k*ALD);
        float4 a1 = *(const float4*)(ap + k*ALD + 4);
        float wv[4] = {w4.x, w4.y, w4.z, w4.w};
        float av[8] = {a0.x, a0.y, a0.z, a0.w, a1.x, a1.y, a1.z, a1.w};
        #pragma unroll
        for (int i = 0; i < 8; i++)
            #pragma unroll
            for (int j = 0; j < 4; j++)
                acc[i][j] = fmaf(av[i], wv[j], acc[i][j]);
    }

    #pragma unroll
    for (int i = 0; i < 8; i++) {
        int r = row0 + ty*8 + i;
        #pragma unroll
        for (int j = 0; j < 4; j++) {
            int c = tx*4 + j;
            float v = acc[i][j] + b[c];
            if (post_act) v = ssp(v);
            if (res) {
                float rv = res[(size_t)r*FF + c];
                v += gate ? gate[c]*rv : rv;
            }
            out[(size_t)r*FF + c] = v;
        }
    }
}

// -------- einsum + gather + aggregate: v[bn,f] += sum_m (rbf[bn,m,:]·k2f[f,:]) * xa[b, nbr[bn,m], f]
#define EWLD 132  // w_s / G_s row stride

__global__ void __launch_bounds__(256) k_einsum(
    const float* __restrict__ rbf, const int* __restrict__ nbr,
    const float* __restrict__ k2f)
{
    extern __shared__ float sm[];
    float* w_s   = sm;                       // [64][EWLD]  w_s[k][f] = k2f[f][k]
    float* rbf_s = sm + KK*EWLD;             // [64][64]
    float* G_s   = rbf_s + MM*KK;            // [64][EWLD]
    float* part  = G_s + MM*EWLD;            // [2][128]
    __shared__ int nbr_s[MM];

    const int tid = threadIdx.x;
    const int bn  = blockIdx.x;              // 0..8191
    const int bb  = bn >> 8;                 // batch

    // load k2f transposed (coalesced)
    for (int idx = tid; idx < FF*KK; idx += 256) {
        int f = idx >> 6, k = idx & 63;
        w_s[k*EWLD + f] = k2f[idx];
    }
    // load rbf tile (contiguous 4096 floats)
    const float* rb = rbf + (size_t)bn*MM*KK;
    for (int idx = tid; idx < MM*KK; idx += 256) rbf_s[idx] = rb[idx];
    if (tid < MM) nbr_s[tid] = nbr[(size_t)bn*MM + tid];
    __syncthreads();

    // phase 1: G[m][f] = sum_k rbf[m][k] * w[k][f]   (4m x 8f register tile)
    {
        const int tx = tid & 15;   // f group: f = tx*8 .. tx*8+7
        const int ty = tid >> 4;   // m group: m = ty*4 .. ty*4+3
        float g[4][8];
        #pragma unroll
        for (int i = 0; i < 4; i++)
            #pragma unroll
            for (int j = 0; j < 8; j++) g[i][j] = 0.0f;

        const float* wp = w_s + tx*8;
        #pragma unroll 2
        for (int k = 0; k < KK; k++) {
            float a[4];
            #pragma unroll
            for (int i = 0; i < 4; i++) a[i] = rbf_s[(ty*4 + i)*KK + k];
            float4 w0 = *(const float4*)(wp + k*EWLD);
            float4 w1 = *(const float4*)(wp + k*EWLD + 4);
            float wv[8] = {w0.x, w0.y, w0.z, w0.w, w1.x, w1.y, w1.z, w1.w};
            #pragma unroll
            for (int i = 0; i < 4; i++)
                #pragma unroll
                for (int j = 0; j < 8; j++)
                    g[i][j] = fmaf(a[i], wv[j], g[i][j]);
        }
        #pragma unroll
        for (int i = 0; i < 4; i++) {
            float* gp = G_s + (ty*4 + i)*EWLD + tx*8;
            *(float4*)(gp)     = make_float4(g[i][0], g[i][1], g[i][2], g[i][3]);
            *(float4*)(gp + 4) = make_float4(g[i][4], g[i][5], g[i][6], g[i][7]);
        }
    }
    __syncthreads();

    // phase 2: xj[f] = sum_m G[m][f] * xa[b, nbr[m], f]; two m-halves in parallel
    {
        const int f = tid & 127;
        const int h = tid >> 7;
        const float* xab = g_xa + (size_t)bb*NN*FF;
        float acc = 0.0f;
        #pragma unroll
        for (int m = h*32; m < h*32 + 32; m++) {
            acc = fmaf(G_s[m*EWLD + f], xab[(size_t)nbr_s[m]*FF + f], acc);
        }
        part[h*FF + f] = acc;
    }
    __syncthreads();
    if (tid < FF) {
        g_v[(size_t)bn*FF + tid] += part[tid] + part[FF + tid];
    }
}

// -------- launch sequence --------
extern "C" void kernel_launch(void* const* d_in, const int* in_sizes, int n_in,
                              void* d_out, int out_size)
{
    const float* x    = (const float*)d_in[0];
    const float* rbf  = (const float*)d_in[1];
    const int*   nbr  = (const int*)  d_in[2];
    const float* k2f  = (const float*)d_in[3];
    const float* Wi   = (const float*)d_in[4];
    const float* bi   = (const float*)d_in[5];
    const float* iW1  = (const float*)d_in[6];
    const float* ib1  = (const float*)d_in[7];
    const float* iW2  = (const float*)d_in[8];
    const float* ib2  = (const float*)d_in[9];
    const float* Wint = (const float*)d_in[10];
    const float* bint = (const float*)d_in[11];
    const float* ug   = (const float*)d_in[12];
    const float* aW1  = (const float*)d_in[13];
    const float* ab1  = (const float*)d_in[14];
    const float* aW2  = (const float*)d_in[15];
    const float* ab2  = (const float*)d_in[16];
    float* out = (float*)d_out;

    float *xa, *v, *t;
    cudaGetSymbolAddress((void**)&xa, g_xa);
    cudaGetSymbolAddress((void**)&v,  g_v);
    cudaGetSymbolAddress((void**)&t,  g_t);

    const int GEMM_SMEM = (FF*WLD + FF*ALD) * 4;                       // ~104.4 KB
    const int EIN_SMEM  = (KK*EWLD + MM*KK + MM*EWLD + 2*FF) * 4;      // ~85.0 KB
    cudaFuncSetAttribute(k_gemm,   cudaFuncAttributeMaxDynamicSharedMemorySize, GEMM_SMEM);
    cudaFuncSetAttribute(k_einsum, cudaFuncAttributeMaxDynamicSharedMemorySize, EIN_SMEM);

    // 1) xa = ssp(x)
    k_ssp<<<(RTOT*FF)/256, 256>>>(x);
    // 2) v = xi = ssp(xa @ Wi^T + bi)
    k_gemm<<<RTOT/GRT, 256, GEMM_SMEM>>>(xa, Wi, bi, nullptr, nullptr, v, 0, 1);
    // 3) v += xj  (fused rbf-filter GEMM + neighbor gather + aggregate)
    k_einsum<<<RTOT, 256, EIN_SMEM>>>(rbf, nbr, k2f);
    // 4) interaction residual blocks
    for (int l = 0; l < 3; l++) {
        k_gemm<<<RTOT/GRT, 256, GEMM_SMEM>>>(v, iW1 + l*FF*FF, ib1 + l*FF, nullptr, nullptr, t, 1, 1);
        k_gemm<<<RTOT/GRT, 256, GEMM_SMEM>>>(t, iW2 + l*FF*FF, ib2 + l*FF, v,       nullptr, v, 0, 0);
    }
    // 5) out = u_gate * x + ssp(v) @ Wint^T + bint
    k_gemm<<<RTOT/GRT, 256, GEMM_SMEM>>>(v, Wint, bint, x, ug, out, 1, 0);
    // 6) atom residual blocks
    for (int l = 0; l < 2; l++) {
        k_gemm<<<RTOT/GRT, 256, GEMM_SMEM>>>(out, aW1 + l*FF*FF, ab1 + l*FF, nullptr, nullptr, t,   1, 1);
        k_gemm<<<RTOT/GRT, 256, GEMM_SMEM>>>(t,   aW2 + l*FF*FF, ab2 + l*FF, out,     nullptr, out, 0, 0);
    }
}

// round 5
// speedup vs baseline: 1.0510x; 1.0510x over previous
#include <cuda_runtime.h>
#include <math.h>

#define BB   32
#define NN   256
#define MM   64
#define FF   128
#define KK   64
#define RTOT (BB*NN)   // 8192

typedef unsigned long long u64;

// -------- scratch (no allocations allowed) --------
__device__ float g_xa[RTOT*FF];
__device__ float g_v [RTOT*FF];
__device__ float g_t [RTOT*FF];

__device__ __forceinline__ float ssp(float x) {
    // softplus(x) - ln2, numerically stable
    float ax = fabsf(x);
    return fmaxf(x, 0.0f) + log1pf(__expf(-ax)) - 0.69314718055994530942f;
}

// ---- packed f32x2 helpers (sm_103a FFMA2 path) ----
__device__ __forceinline__ u64 dup2(float v) {
    u64 r; asm("mov.b64 %0, {%1, %1};" : "=l"(r) : "f"(v)); return r;
}
__device__ __forceinline__ void unpack2(u64 p, float& lo, float& hi) {
    asm("mov.b64 {%0, %1}, %2;" : "=f"(lo), "=f"(hi) : "l"(p));
}
__device__ __forceinline__ u64 ffma2(u64 a, u64 b, u64 c) {
    u64 d; asm("fma.rn.f32x2 %0, %1, %2, %3;" : "=l"(d) : "l"(a), "l"(b), "l"(c)); return d;
}

// -------- elementwise: xa = ssp(x), vectorized --------
__global__ void k_ssp(const float4* __restrict__ x) {
    int i = blockIdx.x * blockDim.x + threadIdx.x;
    float4 v = x[i];
    v.x = ssp(v.x); v.y = ssp(v.y); v.z = ssp(v.z); v.w = ssp(v.w);
    ((float4*)g_xa)[i] = v;
}

// -------- fused GEMM: out[r][c] = maybe_ssp( sum_k pre(in[r][k])*W[c][k] + b[c] ) (+ gate*res | res)
// 64 rows x 64 cols per CTA (grid = 128 x 2 = 256 CTAs), 256 threads.
// Thread tile 8 rows x 2 cols, rows packed in f32x2 pairs -> 8 ffma2 / k.
#define GRT  64
#define GCT  64
#define SSTR 68   // smem row stride (words) for both W_s and A_s

__global__ void __launch_bounds__(256) k_gemm(
    const float* __restrict__ in, const float* __restrict__ W,
    const float* __restrict__ b,  const float* __restrict__ res,
    const float* __restrict__ gate, float* __restrict__ out,
    int pre_act, int post_act)
{
    extern __shared__ float sm[];
    float* W_s = sm;               // [128][SSTR]  W_s[k][c_local]
    float* A_s = sm + FF*SSTR;     // [128][SSTR]  A_s[k][r_local]

    const int tid  = threadIdx.x;
    const int row0 = blockIdx.x * GRT;
    const int c0   = blockIdx.y * GCT;

    // stage W tile transposed (coalesced global reads)
    for (int idx = tid; idx < GCT*FF; idx += 256) {
        int c = idx >> 7, k = idx & 127;
        W_s[k*SSTR + c] = W[(size_t)(c0 + c)*FF + k];
    }
    // stage A tile transposed with optional pre-activation
    for (int idx = tid; idx < GRT*FF; idx += 256) {
        int r = idx >> 7, k = idx & 127;
        float a = in[(size_t)row0*FF + idx];
        if (pre_act) a = ssp(a);
        A_s[k*SSTR + r] = a;
    }
    __syncthreads();

    const int tx = tid & 31;   // cols: c0 + tx*2 .. +1
    const int ty = tid >> 5;   // rows: row0 + ty*8 .. +7

    u64 acc[4][2];
    #pragma unroll
    for (int p = 0; p < 4; p++) { acc[p][0] = 0ull; acc[p][1] = 0ull; }

    const float* ap = A_s + ty*8;
    const float* wp = W_s + tx*2;

    #pragma unroll 8
    for (int k = 0; k < FF; k++) {
        ulonglong2 a01 = *(const ulonglong2*)(ap + k*SSTR);      // row pairs 0,1
        ulonglong2 a23 = *(const ulonglong2*)(ap + k*SSTR + 4);  // row pairs 2,3
        float2 w2 = *(const float2*)(wp + k*SSTR);
        u64 w0 = dup2(w2.x), w1 = dup2(w2.y);
        acc[0][0] = ffma2(a01.x, w0, acc[0][0]);
        acc[0][1] = ffma2(a01.x, w1, acc[0][1]);
        acc[1][0] = ffma2(a01.y, w0, acc[1][0]);
        acc[1][1] = ffma2(a01.y, w1, acc[1][1]);
        acc[2][0] = ffma2(a23.x, w0, acc[2][0]);
        acc[2][1] = ffma2(a23.x, w1, acc[2][1]);
        acc[3][0] = ffma2(a23.y, w0, acc[3][0]);
        acc[3][1] = ffma2(a23.y, w1, acc[3][1]);
    }

    const int cc = c0 + tx*2;
    const float bv0 = b[cc], bv1 = b[cc+1];
    float gv0 = 1.0f, gv1 = 1.0f;
    if (gate) { gv0 = gate[cc]; gv1 = gate[cc+1]; }

    #pragma unroll
    for (int p = 0; p < 4; p++) {
        float v0lo, v0hi, v1lo, v1hi;
        unpack2(acc[p][0], v0lo, v0hi);
        unpack2(acc[p][1], v1lo, v1hi);
        int r = row0 + ty*8 + p*2;
        float o00 = v0lo + bv0, o01 = v1lo + bv1;  // row r
        float o10 = v0hi + bv0, o11 = v1hi + bv1;  // row r+1
        if (post_act) { o00 = ssp(o00); o01 = ssp(o01); o10 = ssp(o10); o11 = ssp(o11); }
        if (res) {
            float2 r0 = *(const float2*)(res + (size_t)r*FF + cc);
            float2 r1 = *(const float2*)(res + (size_t)(r+1)*FF + cc);
            o00 += gv0*r0.x; o01 += gv1*r0.y;
            o10 += gv0*r1.x; o11 += gv1*r1.y;
        }
        *(float2*)(out + (size_t)r*FF + cc)     = make_float2(o00, o01);
        *(float2*)(out + (size_t)(r+1)*FF + cc) = make_float2(o10, o11);
    }
}

// -------- einsum + gather + aggregate: v[bn,f] += sum_m (rbf[bn,m,:]·k2f[f,:]) * xa[b, nbr[bn,m], f]
#define RSTR 68    // rbf_s row stride (k-major, m contiguous)
#define GSTR 132   // w_s / G_s row stride

__global__ void __launch_bounds__(256) k_einsum(
    const float* __restrict__ rbf, const int* __restrict__ nbr,
    const float* __restrict__ k2f)
{
    extern __shared__ float sm[];
    float* w_s   = sm;                       // [64][GSTR]   w_s[k][f] = k2f[f][k]
    float* rbf_s = sm + KK*GSTR;             // [64][RSTR]   rbf_s[k][m]
    float* G_s   = rbf_s + KK*RSTR;          // [64][GSTR]   G_s[m][f]
    float* part  = G_s + MM*GSTR;            // [2][128]
    __shared__ int nbr_s[MM];

    const int tid = threadIdx.x;
    const int bn  = blockIdx.x;              // 0..8191
    const int bb  = bn >> 8;                 // batch

    // stage k2f transposed (coalesced: k fastest)
    for (int idx = tid; idx < FF*KK; idx += 256) {
        int f = idx >> 6, k = idx & 63;
        w_s[k*GSTR + f] = k2f[idx];
    }
    // stage rbf tile transposed to k-major (coalesced reads)
    const float* rb = rbf + (size_t)bn*MM*KK;
    for (int idx = tid; idx < MM*KK; idx += 256) {
        int m = idx >> 6, k = idx & 63;
        rbf_s[k*RSTR + m] = rb[idx];
    }
    if (tid < MM) nbr_s[tid] = nbr[(size_t)bn*MM + tid];
    __syncthreads();

    // phase 1: G[m][f] = sum_k rbf[m][k] * w[k][f]
    // thread tile 8m x 4f, m packed in f32x2 pairs -> 16 ffma2 / k
    {
        const int ty = tid & 7;    // m0 = ty*8
        const int tx = tid >> 3;   // f0 = tx*4
        const float* ap = rbf_s + ty*8;
        const float* wp = w_s + tx*4;

        u64 acc[4][4];
        #pragma unroll
        for (int p = 0; p < 4; p++)
            #pragma unroll
            for (int j = 0; j < 4; j++) acc[p][j] = 0ull;

        #pragma unroll 4
        for (int k = 0; k < KK; k++) {
            ulonglong2 a01 = *(const ulonglong2*)(ap + k*RSTR);      // m pairs 0,1
            ulonglong2 a23 = *(const ulonglong2*)(ap + k*RSTR + 4);  // m pairs 2,3
            float4 w4 = *(const float4*)(wp + k*GSTR);
            u64 wd[4] = { dup2(w4.x), dup2(w4.y), dup2(w4.z), dup2(w4.w) };
            u64 am[4] = { a01.x, a01.y, a23.x, a23.y };
            #pragma unroll
            for (int p = 0; p < 4; p++)
                #pragma unroll
                for (int j = 0; j < 4; j++)
                    acc[p][j] = ffma2(am[p], wd[j], acc[p][j]);
        }

        // write G_s[m][f]
        #pragma unroll
        for (int p = 0; p < 4; p++) {
            float lo[4], hi[4];
            #pragma unroll
            for (int j = 0; j < 4; j++) unpack2(acc[p][j], lo[j], hi[j]);
            int m = ty*8 + p*2;
            *(float4*)(G_s + m*GSTR + tx*4)     = make_float4(lo[0], lo[1], lo[2], lo[3]);
            *(float4*)(G_s + (m+1)*GSTR + tx*4) = make_float4(hi[0], hi[1], hi[2], hi[3]);
        }
    }
    __syncthreads();

    // phase 2: xj[f] = sum_m G[m][f] * xa[b, nbr[m], f]; two m-halves in parallel
    {
        const int f = tid & 127;
        const int h = tid >> 7;
        const float* xab = g_xa + (size_t)bb*NN*FF;
        float acc = 0.0f;
        #pragma unroll
        for (int m = h*32; m < h*32 + 32; m++) {
            acc = fmaf(G_s[m*GSTR + f], __ldg(xab + (size_t)nbr_s[m]*FF + f), acc);
        }
        part[h*FF + f] = acc;
    }
    __syncthreads();
    if (tid < FF) {
        g_v[(size_t)bn*FF + tid] += part[tid] + part[FF + tid];
    }
}

// -------- launch sequence --------
extern "C" void kernel_launch(void* const* d_in, const int* in_sizes, int n_in,
                              void* d_out, int out_size)
{
    const float* x    = (const float*)d_in[0];
    const float* rbf  = (const float*)d_in[1];
    const int*   nbr  = (const int*)  d_in[2];
    const float* k2f  = (const float*)d_in[3];
    const float* Wi   = (const float*)d_in[4];
    const float* bi   = (const float*)d_in[5];
    const float* iW1  = (const float*)d_in[6];
    const float* ib1  = (const float*)d_in[7];
    const float* iW2  = (const float*)d_in[8];
    const float* ib2  = (const float*)d_in[9];
    const float* Wint = (const float*)d_in[10];
    const float* bint = (const float*)d_in[11];
    const float* ug   = (const float*)d_in[12];
    const float* aW1  = (const float*)d_in[13];
    const float* ab1  = (const float*)d_in[14];
    const float* aW2  = (const float*)d_in[15];
    const float* ab2  = (const float*)d_in[16];
    float* out = (float*)d_out;

    float *xa, *v, *t;
    cudaGetSymbolAddress((void**)&xa, g_xa);
    cudaGetSymbolAddress((void**)&v,  g_v);
    cudaGetSymbolAddress((void**)&t,  g_t);

    const int GEMM_SMEM = (2*FF*SSTR) * 4;                               // 69.6 KB
    const int EIN_SMEM  = (KK*GSTR + KK*RSTR + MM*GSTR + 2*FF) * 4;      // 86.1 KB
    cudaFuncSetAttribute(k_gemm,   cudaFuncAttributeMaxDynamicSharedMemorySize, GEMM_SMEM);
    cudaFuncSetAttribute(k_einsum, cudaFuncAttributeMaxDynamicSharedMemorySize, EIN_SMEM);

    dim3 ggrid(RTOT/GRT, FF/GCT);   // 128 x 2

    // 1) xa = ssp(x)
    k_ssp<<<(RTOT*FF/4)/256, 256>>>((const float4*)x);
    // 2) v = xi = ssp(xa @ Wi^T + bi)
    k_gemm<<<ggrid, 256, GEMM_SMEM>>>(xa, Wi, bi, nullptr, nullptr, v, 0, 1);
    // 3) v += xj  (fused rbf-filter GEMM + neighbor gather + aggregate)
    k_einsum<<<RTOT, 256, EIN_SMEM>>>(rbf, nbr, k2f);
    // 4) interaction residual blocks
    for (int l = 0; l < 3; l++) {
        k_gemm<<<ggrid, 256, GEMM_SMEM>>>(v, iW1 + l*FF*FF, ib1 + l*FF, nullptr, nullptr, t, 1, 1);
        k_gemm<<<ggrid, 256, GEMM_SMEM>>>(t, iW2 + l*FF*FF, ib2 + l*FF, v,       nullptr, v, 0, 0);
    }
    // 5) out = u_gate * x + ssp(v) @ Wint^T + bint
    k_gemm<<<ggrid, 256, GEMM_SMEM>>>(v, Wint, bint, x, ug, out, 1, 0);
    // 6) atom residual blocks
    for (int l = 0; l < 2; l++) {
        k_gemm<<<ggrid, 256, GEMM_SMEM>>>(out, aW1 + l*FF*FF, ab1 + l*FF, nullptr, nullptr, t,   1, 1);
        k_gemm<<<ggrid, 256, GEMM_SMEM>>>(t,   aW2 + l*FF*FF, ab2 + l*FF, out,     nullptr, out, 0, 0);
    }
}